// round 2
// baseline (speedup 1.0000x reference)
#include <cuda_runtime.h>

// Problem constants
#define KK 4
#define MM 32
#define DD 2048
#define TT 128
#define TC 8            // t-columns per CTA (one 32B sector)
#define NTHREADS 256

// smem layout (floats):
//   xch : 8 t-columns * 2116 padded floats (64 rows * 33 + pad) = 16928
//   spar: 4 arrays * 32 chunks * 68 padded floats               =  8704
#define PSTRIDE 33              // row stride inside one t-column (p*33 + c)
#define XCH_STRIDE 2116         // per-t-column stride; == 4 (mod 32)
#define XCH_FLOATS (8 * XCH_STRIDE)
#define PAR_STRIDE 2176         // 32 * 68
#define PAR_FLOATS (4 * PAR_STRIDE)
#define SMEM_BYTES ((XCH_FLOATS + PAR_FLOATS) * 4)

// 1/sqrt(2048) — folded into each diagonal to normalize each H
#define HNORM 0.022097086912079608f

__global__ __launch_bounds__(NTHREADS, 2)
void spinner_main_kernel(const float* __restrict__ z,
                         const float* __restrict__ d1,
                         const float* __restrict__ d2,
                         const float* __restrict__ d3,
                         const float* __restrict__ bia,
                         float* __restrict__ out)
{
    extern __shared__ float smem[];
    float* xch  = smem;                 // transpose buffer
    float* spar = smem + XCH_FLOATS;    // scaled diagonals + bias, layout [a][c*68+p]

    const int tid = threadIdx.x;
    const int km  = blockIdx.x >> 4;          // (k*M+m)
    const int t0  = (blockIdx.x & 15) * TC;   // t-block start

    // Stage params into smem
    for (int i = tid; i < DD; i += NTHREADS) {
        int c = i >> 6, p = i & 63;
        int off = c * 68 + p;
        spar[0 * PAR_STRIDE + off] = d1[i] * HNORM;
        spar[1 * PAR_STRIDE + off] = d2[i] * HNORM;
        spar[2 * PAR_STRIDE + off] = d3[i] * HNORM;
        spar[3 * PAR_STRIDE + off] = bia[i];
    }
    __syncthreads();

    const int t  = tid & 7;    // this thread's t-column within the tile
    const int cc = tid >> 3;   // phase-1: d-chunk index (d = cc*64 + p), 0..31
    const int g  = tid >> 3;   // phase-2: p rows {g, g+32},            0..31

    const float* zin = z + (size_t)km * (DD * TT) + (t0 + t);
    float x[64];

    // ---- load + scale by d1/sqrt(D) (phase-1: p = 0..63 at chunk c = cc) ----
    {
        const float* zp = zin + (size_t)cc * 64 * TT;
        const float* s1 = spar + 0 * PAR_STRIDE + cc * 68;
        #pragma unroll
        for (int p = 0; p < 64; ++p)
            x[p] = zp[(size_t)p * TT] * s1[p];
    }

    // ---- FWHT #1: H_64 over p (local) ----
    #pragma unroll
    for (int h = 1; h < 64; h <<= 1) {
        #pragma unroll
        for (int i = 0; i < 64; ++i)
            if ((i & h) == 0) {
                float a = x[i], b = x[i | h];
                x[i] = a + b; x[i | h] = a - b;
            }
    }

    float* xc = xch + t * XCH_STRIDE;

    // exchange E1: phase-1 -> phase-2  (registers end up indexed by TRUE c)
    #pragma unroll
    for (int p = 0; p < 64; ++p)
        xc[p * PSTRIDE + cc] = x[p];
    __syncthreads();
    #pragma unroll
    for (int j = 0; j < 32; ++j) {
        x[j]      = xc[g        * PSTRIDE + j];   // (c=j, p=g)
        x[32 + j] = xc[(g + 32) * PSTRIDE + j];   // (c=j, p=g+32)
    }

    // ---- FWHT #1: H_32 over c (local, true index, no sign twist) ----
    #pragma unroll
    for (int h = 1; h < 32; h <<= 1) {
        #pragma unroll
        for (int j = 0; j < 32; ++j)
            if ((j & h) == 0) {
                float a = x[j],       b = x[j | h];
                x[j] = a + b;         x[j | h] = a - b;
                float a2 = x[32 + j], b2 = x[32 + (j | h)];
                x[32 + j] = a2 + b2;  x[32 + (j | h)] = a2 - b2;
            }
    }

    // ---- scale by d2/sqrt(D) (phase-2: d = j*64 + g / j*64 + g+32) ----
    #pragma unroll
    for (int j = 0; j < 32; ++j) {
        const float* s2 = spar + 1 * PAR_STRIDE + j * 68;
        x[j]      *= s2[g];
        x[32 + j] *= s2[g + 32];
    }

    // ---- FWHT #2: H_32 over c (local) ----
    #pragma unroll
    for (int h = 1; h < 32; h <<= 1) {
        #pragma unroll
        for (int j = 0; j < 32; ++j)
            if ((j & h) == 0) {
                float a = x[j],       b = x[j | h];
                x[j] = a + b;         x[j | h] = a - b;
                float a2 = x[32 + j], b2 = x[32 + (j | h)];
                x[32 + j] = a2 + b2;  x[32 + (j | h)] = a2 - b2;
            }
    }

    // exchange E2: phase-2 -> phase-1
    __syncthreads();
    #pragma unroll
    for (int j = 0; j < 32; ++j) {
        xc[g        * PSTRIDE + j] = x[j];
        xc[(g + 32) * PSTRIDE + j] = x[32 + j];
    }
    __syncthreads();
    #pragma unroll
    for (int p = 0; p < 64; ++p)
        x[p] = xc[p * PSTRIDE + cc];

    // ---- FWHT #2: H_64 over p (local) ----
    #pragma unroll
    for (int h = 1; h < 64; h <<= 1) {
        #pragma unroll
        for (int i = 0; i < 64; ++i)
            if ((i & h) == 0) {
                float a = x[i], b = x[i | h];
                x[i] = a + b; x[i | h] = a - b;
            }
    }

    // ---- scale by d3/sqrt(D) (phase-1 layout) ----
    {
        const float* s3 = spar + 2 * PAR_STRIDE + cc * 68;
        #pragma unroll
        for (int p = 0; p < 64; ++p)
            x[p] *= s3[p];
    }

    // ---- FWHT #3: H_64 over p (local) ----
    #pragma unroll
    for (int h = 1; h < 64; h <<= 1) {
        #pragma unroll
        for (int i = 0; i < 64; ++i)
            if ((i & h) == 0) {
                float a = x[i], b = x[i | h];
                x[i] = a + b; x[i | h] = a - b;
            }
    }

    // exchange E3: phase-1 -> phase-2
    __syncthreads();
    #pragma unroll
    for (int p = 0; p < 64; ++p)
        xc[p * PSTRIDE + cc] = x[p];
    __syncthreads();
    #pragma unroll
    for (int j = 0; j < 32; ++j) {
        x[j]      = xc[g        * PSTRIDE + j];
        x[32 + j] = xc[(g + 32) * PSTRIDE + j];
    }

    // ---- FWHT #3: H_32 over c (local) ----
    #pragma unroll
    for (int h = 1; h < 32; h <<= 1) {
        #pragma unroll
        for (int j = 0; j < 32; ++j)
            if ((j & h) == 0) {
                float a = x[j],       b = x[j | h];
                x[j] = a + b;         x[j | h] = a - b;
                float a2 = x[32 + j], b2 = x[32 + (j | h)];
                x[32 + j] = a2 + b2;  x[32 + (j | h)] = a2 - b2;
            }
    }

    // ---- bias + store (phase-2; stores 32B-sector coalesced over t) ----
    float* zout = out + (size_t)km * (DD * TT) + (t0 + t);
    #pragma unroll
    for (int j = 0; j < 32; ++j) {
        const float* bb = spar + 3 * PAR_STRIDE + j * 68;
        zout[(size_t)(j * 64 + g)      * TT] = x[j]      + bb[g];
        zout[(size_t)(j * 64 + g + 32) * TT] = x[32 + j] + bb[g + 32];
    }
}

__global__ void spinner_sldj_kernel(const float* __restrict__ d1,
                                    const float* __restrict__ d2,
                                    const float* __restrict__ d3,
                                    const float* __restrict__ sldj_in,
                                    float* __restrict__ out)
{
    __shared__ float red[256];
    int tid = threadIdx.x;
    float s = 0.f;
    for (int i = tid; i < DD; i += 256)
        s += logf(fabsf(d1[i])) + logf(fabsf(d2[i])) + logf(fabsf(d3[i]));
    red[tid] = s;
    __syncthreads();
    #pragma unroll
    for (int w = 128; w > 0; w >>= 1) {
        if (tid < w) red[tid] += red[tid + w];
        __syncthreads();
    }
    float ld = red[0];
    if (tid < KK * MM)
        out[(size_t)KK * MM * DD * TT + tid] = sldj_in[tid] + ld;
}

extern "C" void kernel_launch(void* const* d_in, const int* in_sizes, int n_in,
                              void* d_out, int out_size)
{
    (void)in_sizes; (void)n_in; (void)out_size;
    const float* z    = (const float*)d_in[0];
    const float* d1   = (const float*)d_in[1];
    const float* d2   = (const float*)d_in[2];
    const float* d3   = (const float*)d_in[3];
    const float* bia  = (const float*)d_in[4];
    const float* sldj = (const float*)d_in[5];
    float* out = (float*)d_out;

    cudaFuncSetAttribute(spinner_main_kernel,
                         cudaFuncAttributeMaxDynamicSharedMemorySize, SMEM_BYTES);

    // grid: (K*M) * (T / TC) = 128 * 16 = 2048 CTAs
    spinner_main_kernel<<<KK * MM * (TT / TC), NTHREADS, SMEM_BYTES>>>(
        z, d1, d2, d3, bia, out);
    spinner_sldj_kernel<<<1, 256>>>(d1, d2, d3, sldj, out);
}

// round 3
// speedup vs baseline: 1.1562x; 1.1562x over previous
#include <cuda_runtime.h>

// Problem constants
#define KK 4
#define MM 32
#define DD 2048
#define TT 128
#define TC 8            // t-columns per CTA (one 32B sector)
#define NTHREADS 256

typedef unsigned long long u64;

// smem layout (u64 = packed float2 units):
//   xch : 8 t-columns * 1058 (32 rows * 33 + pad; 1058 % 16 == 2)  = 8464
//   spar: 4 arrays * 32 chunks * 33                                 = 4224
#define PST 33          // row stride inside a t-column (p*33 + c), odd
#define XS  1058        // per-t-column stride (== 2 mod 16)
#define XCH_U64 (8 * XS)
#define PAR_STRIDE 1056 // 32*33
#define PAR_U64 (4 * PAR_STRIDE)
#define SMEM_BYTES ((XCH_U64 + PAR_U64) * 8)

// 1/sqrt(2048) — folded into each diagonal
#define HNORM 0.022097086912079608f

// ---- packed f32x2 helpers (sm_103a) ----
__device__ __forceinline__ u64 addx2(u64 a, u64 b) {
    u64 r; asm("add.rn.f32x2 %0,%1,%2;" : "=l"(r) : "l"(a), "l"(b)); return r;
}
__device__ __forceinline__ u64 subx2(u64 a, u64 b) {
    u64 r; asm("sub.rn.f32x2 %0,%1,%2;" : "=l"(r) : "l"(a), "l"(b)); return r;
}
__device__ __forceinline__ u64 mulx2(u64 a, u64 b) {
    u64 r; asm("mul.rn.f32x2 %0,%1,%2;" : "=l"(r) : "l"(a), "l"(b)); return r;
}
__device__ __forceinline__ u64 pk(float lo, float hi) {
    u64 r; asm("mov.b64 %0,{%1,%2};" : "=l"(r) : "f"(lo), "f"(hi)); return r;
}
__device__ __forceinline__ void upk(float& lo, float& hi, u64 v) {
    asm("mov.b64 {%0,%1},%2;" : "=f"(lo), "=f"(hi) : "l"(v));
}

#define BFLY(A, B) { u64 _a = (A), _b = (B); (A) = addx2(_a, _b); (B) = subx2(_a, _b); }

// packed H32 over register index bits (5 stages, y[0..31])
#define H32_PACKED(y) \
    { _Pragma("unroll") for (int h = 1; h < 32; h <<= 1) { \
        _Pragma("unroll") for (int j = 0; j < 32; ++j) \
            if ((j & h) == 0) BFLY(y[j], y[j | h]); } }

// intra-pair (h=32) butterfly over packed (p, p+32)
#define H64_TOP(y) \
    { _Pragma("unroll") for (int p = 0; p < 32; ++p) { \
        float _lo, _hi; upk(_lo, _hi, y[p]); \
        y[p] = pk(_lo + _hi, _lo - _hi); } }

__global__ __launch_bounds__(NTHREADS, 2)
void spinner_main_kernel(const float* __restrict__ z,
                         const float* __restrict__ d1,
                         const float* __restrict__ d2,
                         const float* __restrict__ d3,
                         const float* __restrict__ bia,
                         const float* __restrict__ sldj_in,
                         float* __restrict__ out)
{
    extern __shared__ u64 smem8[];
    const int tid = threadIdx.x;

    // ---- block 2048: sldj tail (runs concurrently with the main tiles) ----
    if (blockIdx.x == KK * MM * (TT / TC)) {
        float* red = (float*)smem8;
        float s = 0.f;
        for (int i = tid; i < DD; i += NTHREADS)
            s += logf(fabsf(d1[i])) + logf(fabsf(d2[i])) + logf(fabsf(d3[i]));
        red[tid] = s;
        __syncthreads();
        #pragma unroll
        for (int w = 128; w > 0; w >>= 1) {
            if (tid < w) red[tid] += red[tid + w];
            __syncthreads();
        }
        float ld = red[0];
        if (tid < KK * MM)
            out[(size_t)KK * MM * DD * TT + tid] = sldj_in[tid] + ld;
        return;
    }

    u64* xch  = smem8;             // transpose buffer (packed pairs)
    u64* spar = smem8 + XCH_U64;   // packed params: (v[c*64+p], v[c*64+p+32]) at [a][c*33+p]

    // Stage params (packed) into smem
    for (int i = tid; i < 1024; i += NTHREADS) {
        int c = i >> 5, p = i & 31;
        int base = c * 64 + p, off = c * PST + p;
        spar[0 * PAR_STRIDE + off] = pk(d1[base] * HNORM, d1[base + 32] * HNORM);
        spar[1 * PAR_STRIDE + off] = pk(d2[base] * HNORM, d2[base + 32] * HNORM);
        spar[2 * PAR_STRIDE + off] = pk(d3[base] * HNORM, d3[base + 32] * HNORM);
        spar[3 * PAR_STRIDE + off] = pk(bia[base], bia[base + 32]);
    }
    __syncthreads();

    const int km = blockIdx.x >> 4;          // (k*M+m)
    const int t0 = (blockIdx.x & 15) * TC;   // t-block start
    const int t  = tid & 7;                  // t-column within tile
    const int cc = tid >> 3;                 // phase-1 chunk (d = cc*64 + p)
    const int g  = cc;                       // phase-2 p rows {g, g+32}

    const float* zin = z + (size_t)km * (DD * TT) + (size_t)cc * 64 * TT + (t0 + t);
    u64 y[32];   // packed (p, p+32) in phase-1; (p=g, p=g+32) per c in phase-2

    // ---- load + d1 scale + H64 h=32 stage (folded) ----
    {
        const u64* s1 = spar + 0 * PAR_STRIDE + cc * PST;
        #pragma unroll
        for (int p = 0; p < 32; ++p) {
            float a = zin[(size_t)p * TT];
            float b = zin[(size_t)(p + 32) * TT];
            float slo, shi; upk(slo, shi, s1[p]);
            a *= slo; b *= shi;
            y[p] = pk(a + b, a - b);
        }
    }

    // ---- FWHT #1: H64 remaining stages (packed over p-bits 1..16) ----
    H32_PACKED(y);

    u64* xc = xch + t * XS;

    // E1: phase-1 -> phase-2
    #pragma unroll
    for (int p = 0; p < 32; ++p) xc[p * PST + cc] = y[p];
    __syncthreads();
    #pragma unroll
    for (int j = 0; j < 32; ++j) y[j] = xc[g * PST + j];

    // ---- FWHT #1: H32 over c (both packed lanes independent) ----
    H32_PACKED(y);

    // ---- d2 scale (packed) ----
    #pragma unroll
    for (int j = 0; j < 32; ++j)
        y[j] = mulx2(y[j], spar[1 * PAR_STRIDE + j * PST + g]);

    // ---- FWHT #2: H32 over c ----
    H32_PACKED(y);

    // E2: phase-2 -> phase-1
    __syncthreads();
    #pragma unroll
    for (int j = 0; j < 32; ++j) xc[g * PST + j] = y[j];
    __syncthreads();
    #pragma unroll
    for (int p = 0; p < 32; ++p) y[p] = xc[p * PST + cc];

    // ---- FWHT #2: H64 over p (5 packed stages + intra-pair stage) ----
    H32_PACKED(y);
    H64_TOP(y);

    // ---- d3 scale (packed) ----
    {
        const u64* s3 = spar + 2 * PAR_STRIDE + cc * PST;
        #pragma unroll
        for (int p = 0; p < 32; ++p) y[p] = mulx2(y[p], s3[p]);
    }

    // ---- FWHT #3: H64 over p ----
    H64_TOP(y);
    H32_PACKED(y);

    // E3: phase-1 -> phase-2
    __syncthreads();
    #pragma unroll
    for (int p = 0; p < 32; ++p) xc[p * PST + cc] = y[p];
    __syncthreads();
    #pragma unroll
    for (int j = 0; j < 32; ++j) y[j] = xc[g * PST + j];

    // ---- FWHT #3: H32 over c ----
    H32_PACKED(y);

    // ---- bias (packed) + store ----
    float* zout = out + (size_t)km * (DD * TT) + (t0 + t);
    #pragma unroll
    for (int j = 0; j < 32; ++j) {
        u64 r = addx2(y[j], spar[3 * PAR_STRIDE + j * PST + g]);
        float lo, hi; upk(lo, hi, r);
        zout[(size_t)(j * 64 + g)      * TT] = lo;
        zout[(size_t)(j * 64 + g + 32) * TT] = hi;
    }
}

extern "C" void kernel_launch(void* const* d_in, const int* in_sizes, int n_in,
                              void* d_out, int out_size)
{
    (void)in_sizes; (void)n_in; (void)out_size;
    const float* z    = (const float*)d_in[0];
    const float* d1   = (const float*)d_in[1];
    const float* d2   = (const float*)d_in[2];
    const float* d3   = (const float*)d_in[3];
    const float* bia  = (const float*)d_in[4];
    const float* sldj = (const float*)d_in[5];
    float* out = (float*)d_out;

    cudaFuncSetAttribute(spinner_main_kernel,
                         cudaFuncAttributeMaxDynamicSharedMemorySize, SMEM_BYTES);

    // grid: 2048 tile blocks + 1 sldj block
    spinner_main_kernel<<<KK * MM * (TT / TC) + 1, NTHREADS, SMEM_BYTES>>>(
        z, d1, d2, d3, bia, sldj, out);
}

// round 4
// speedup vs baseline: 1.2389x; 1.0716x over previous
#include <cuda_runtime.h>

// Problem constants
#define KK 4
#define MM 32
#define DD 2048
#define TT 128
#define TTILE 16          // t-columns per CTA (64B of each 128B line)
#define NTHREADS 1024

typedef unsigned long long u64;

// smem (u64 units):
//  xch : TTILE t-columns * XS; XS odd -> conflict-free scalar .64 exchanges
//  spar: 4 arrays * 1024 packed params  (broadcast access, no padding needed)
#define PST 32
#define XS  1025                    // 32*32 + 1, odd
#define XCH_U64 (TTILE * XS)        // 16400
#define SPAR 1024
#define SMEM_BYTES ((XCH_U64 + 4 * SPAR) * 8)

#define HNORM 0.022097086912079608f   // 1/sqrt(2048), folded per diagonal

// ---- packed f32x2 helpers (sm_103a) ----
__device__ __forceinline__ u64 addx2(u64 a, u64 b) {
    u64 r; asm("add.rn.f32x2 %0,%1,%2;" : "=l"(r) : "l"(a), "l"(b)); return r;
}
__device__ __forceinline__ u64 subx2(u64 a, u64 b) {
    u64 r; asm("sub.rn.f32x2 %0,%1,%2;" : "=l"(r) : "l"(a), "l"(b)); return r;
}
__device__ __forceinline__ u64 mulx2(u64 a, u64 b) {
    u64 r; asm("mul.rn.f32x2 %0,%1,%2;" : "=l"(r) : "l"(a), "l"(b)); return r;
}
__device__ __forceinline__ u64 pk(float lo, float hi) {
    u64 r; asm("mov.b64 %0,{%1,%2};" : "=l"(r) : "f"(lo), "f"(hi)); return r;
}
__device__ __forceinline__ void upk(float& lo, float& hi, u64 v) {
    asm("mov.b64 {%0,%1},%2;" : "=f"(lo), "=f"(hi) : "l"(v));
}

#define BFLY(A, B) { u64 _a = (A), _b = (B); (A) = addx2(_a, _b); (B) = subx2(_a, _b); }

// local stages s=1,2,4,8 over 16-reg array  (covers index-bit strides h=2..16)
#define LOCAL4(y) \
    { _Pragma("unroll") for (int s = 1; s < 16; s <<= 1) { \
        _Pragma("unroll") for (int j = 0; j < 16; ++j) \
            if ((j & s) == 0) BFLY(y[j], y[j | s]); } }

// cross-thread stage (index bit held by q = lane bit 4); shfl convergent
#define CROSS(y, q) \
    { _Pragma("unroll") for (int i = 0; i < 16; ++i) { \
        u64 _o = __shfl_xor_sync(0xffffffffu, y[i], 16); \
        y[i] = (q) ? subx2(_o, y[i]) : addx2(y[i], _o); } }

// intra-register stage (packed pair = d, d+32)
#define INTRA(y) \
    { _Pragma("unroll") for (int i = 0; i < 16; ++i) { \
        float _lo, _hi; upk(_lo, _hi, y[i]); \
        y[i] = pk(_lo + _hi, _lo - _hi); } }

__global__ __launch_bounds__(NTHREADS, 1)
void spinner_main_kernel(const float* __restrict__ z,
                         const float* __restrict__ d1,
                         const float* __restrict__ d2,
                         const float* __restrict__ d3,
                         const float* __restrict__ bia,
                         const float* __restrict__ sldj_in,
                         float* __restrict__ out)
{
    extern __shared__ u64 smem8[];
    const int tid = threadIdx.x;

    // ---- last block: sldj tail ----
    if (blockIdx.x == KK * MM * (TT / TTILE)) {
        float* red = (float*)smem8;
        float s = 0.f;
        for (int i = tid; i < DD; i += NTHREADS)
            s += logf(fabsf(d1[i])) + logf(fabsf(d2[i])) + logf(fabsf(d3[i]));
        red[tid] = s;
        __syncthreads();
        #pragma unroll
        for (int w = 512; w > 0; w >>= 1) {
            if (tid < w) red[tid] += red[tid + w];
            __syncthreads();
        }
        float ld = red[0];
        if (tid < KK * MM)
            out[(size_t)KK * MM * DD * TT + tid] = sldj_in[tid] + ld;
        return;
    }

    u64* xch  = smem8;
    u64* spar = smem8 + XCH_U64;   // [a][c*32+p] = packed (v[c*64+p], v[c*64+p+32])

    // stage params (tid covers 0..1023 exactly once)
    {
        int c = tid >> 5, p = tid & 31;
        int d = c * 64 + p;
        spar[0 * SPAR + tid] = pk(d1[d] * HNORM, d1[d + 32] * HNORM);
        spar[1 * SPAR + tid] = pk(d2[d] * HNORM, d2[d + 32] * HNORM);
        spar[2 * SPAR + tid] = pk(d3[d] * HNORM, d3[d + 32] * HNORM);
        spar[3 * SPAR + tid] = pk(bia[d], bia[d + 32]);
    }
    __syncthreads();

    const int km = blockIdx.x >> 3;          // (k*M+m)
    const int t0 = (blockIdx.x & 7) * TTILE; // t-block start
    const int t  = tid & 15;                 // t-column (lane bits 0-3)
    const int q  = (tid >> 4) & 1;           // split bit (lane bit 4)
    const int u  = tid >> 5;                 // phase-1: cc; phase-2: g  (0..31)

    const float* zin = z + (size_t)km * (DD * TT) + (t0 + t);
    u64* xc = xch + t * XS;
    u64 y[16];

    // ---- load + d1 scale  (phase-1: d = u*64 + 2i + q, packed with d+32) ----
    #pragma unroll
    for (int i = 0; i < 16; ++i) {
        int dlo = u * 64 + 2 * i + q;
        float lo = zin[(size_t)dlo * TT];
        float hi = zin[(size_t)(dlo + 32) * TT];
        y[i] = mulx2(pk(lo, hi), spar[0 * SPAR + u * 32 + 2 * i + q]);
    }

    // ---- FWHT #1: H64 over p ----
    CROSS(y, q); LOCAL4(y); INTRA(y);

    // E1: phase-1 -> phase-2
    #pragma unroll
    for (int i = 0; i < 16; ++i) xc[(2 * i + q) * PST + u] = y[i];
    __syncthreads();
    #pragma unroll
    for (int j = 0; j < 16; ++j) y[j] = xc[u * PST + 2 * j + q];

    // ---- FWHT #1: H32 over c ----
    CROSS(y, q); LOCAL4(y);

    // ---- d2 scale (phase-2: c = 2j+q, rows u/u+32 packed) ----
    #pragma unroll
    for (int j = 0; j < 16; ++j)
        y[j] = mulx2(y[j], spar[1 * SPAR + (2 * j + q) * 32 + u]);

    // ---- FWHT #2: H32 over c ----
    LOCAL4(y); CROSS(y, q);

    // E2: phase-2 -> phase-1
    __syncthreads();
    #pragma unroll
    for (int j = 0; j < 16; ++j) xc[u * PST + 2 * j + q] = y[j];
    __syncthreads();
    #pragma unroll
    for (int i = 0; i < 16; ++i) y[i] = xc[(2 * i + q) * PST + u];

    // ---- FWHT #2: H64 over p ----
    INTRA(y); LOCAL4(y); CROSS(y, q);

    // ---- d3 scale (phase-1) ----
    #pragma unroll
    for (int i = 0; i < 16; ++i)
        y[i] = mulx2(y[i], spar[2 * SPAR + u * 32 + 2 * i + q]);

    // ---- FWHT #3: H64 over p ----
    CROSS(y, q); LOCAL4(y); INTRA(y);

    // E3: phase-1 -> phase-2
    __syncthreads();
    #pragma unroll
    for (int i = 0; i < 16; ++i) xc[(2 * i + q) * PST + u] = y[i];
    __syncthreads();
    #pragma unroll
    for (int j = 0; j < 16; ++j) y[j] = xc[u * PST + 2 * j + q];

    // ---- FWHT #3: H32 over c ----
    CROSS(y, q); LOCAL4(y);

    // ---- bias + store ----
    float* zout = out + (size_t)km * (DD * TT) + (t0 + t);
    #pragma unroll
    for (int j = 0; j < 16; ++j) {
        u64 r = addx2(y[j], spar[3 * SPAR + (2 * j + q) * 32 + u]);
        float lo, hi; upk(lo, hi, r);
        int dlo = (2 * j + q) * 64 + u;
        zout[(size_t)dlo * TT]        = lo;
        zout[(size_t)(dlo + 32) * TT] = hi;
    }
}

extern "C" void kernel_launch(void* const* d_in, const int* in_sizes, int n_in,
                              void* d_out, int out_size)
{
    (void)in_sizes; (void)n_in; (void)out_size;
    const float* z    = (const float*)d_in[0];
    const float* d1   = (const float*)d_in[1];
    const float* d2   = (const float*)d_in[2];
    const float* d3   = (const float*)d_in[3];
    const float* bia  = (const float*)d_in[4];
    const float* sldj = (const float*)d_in[5];
    float* out = (float*)d_out;

    cudaFuncSetAttribute(spinner_main_kernel,
                         cudaFuncAttributeMaxDynamicSharedMemorySize, SMEM_BYTES);

    // grid: 128 km * 8 t-blocks + 1 sldj block
    spinner_main_kernel<<<KK * MM * (TT / TTILE) + 1, NTHREADS, SMEM_BYTES>>>(
        z, d1, d2, d3, bia, sldj, out);
}